// round 2
// baseline (speedup 1.0000x reference)
#include <cuda_runtime.h>

#define BT     4096      // B*T
#define KCAND  64
#define DK     128
#define DCTX   256
#define DV     128
#define GAMMA  1.0f
#define ETA    1.0f
#define INV_TEMP 1.0f

// 4 MB scratch for Qw = Q @ W_ctx  (device global => allowed, no allocation)
__device__ float g_qw[BT * DCTX];

// ---------------------------------------------------------------------------
// Kernel 1: Qw[row, c] = sum_d Q[row, d] * W_ctx[d, c]
// 16 rows per block => W_ctx re-read only 256x (L2-resident, ~32MB L2 traffic)
// ---------------------------------------------------------------------------
__global__ __launch_bounds__(256) void qw_kernel(const float* __restrict__ Q,
                                                 const float* __restrict__ W) {
    __shared__ float qsh[16][DK];
    const int rowbase = blockIdx.x * 16;
    for (int i = threadIdx.x; i < 16 * DK; i += 256)
        qsh[i >> 7][i & 127] = Q[rowbase * DK + i];
    __syncthreads();

    const int c = threadIdx.x;   // 0..255 = output column
    float acc[16];
#pragma unroll
    for (int r = 0; r < 16; ++r) acc[r] = 0.f;

#pragma unroll 4
    for (int d = 0; d < DK; ++d) {
        const float wv = W[d * DCTX + c];   // coalesced, L2-hot
#pragma unroll
        for (int r = 0; r < 16; ++r)
            acc[r] = fmaf(qsh[r][d], wv, acc[r]);  // smem broadcast, no conflicts
    }
#pragma unroll
    for (int r = 0; r < 16; ++r)
        g_qw[(rowbase + r) * DCTX + c] = acc[r];
}

// ---------------------------------------------------------------------------
// Kernel 2: one block per (b,t) row. 8 warps x 8 candidates.
// ---------------------------------------------------------------------------
__global__ __launch_bounds__(256) void kb_main_kernel(
    const float* __restrict__ Q,
    const float* __restrict__ K_kb,
    const float* __restrict__ V_kb,
    const float* __restrict__ ctx,
    const float* __restrict__ b_ctx,
    const float* __restrict__ rel_emb,
    const float* __restrict__ ent_emb,
    const float* __restrict__ q_min,
    const float* __restrict__ q_max,
    const float* __restrict__ tau_min,
    const float* __restrict__ tau_max,
    const int*   __restrict__ rel_id,
    const int*   __restrict__ ent_id,
    float* __restrict__ out_alpha,
    float* __restrict__ out_v)
{
    __shared__ float4 sm_q4[DK / 4];     // 32 float4
    __shared__ float4 sm_qw4[DCTX / 4];  // 64 float4
    __shared__ float  sm_s[KCAND];       // scores -> alpha
    __shared__ float  sm_vp[DV];         // partial V accumulation

    const int row  = blockIdx.x;
    const int tid  = threadIdx.x;
    const int warp = tid >> 5;
    const int lane = tid & 31;

    // Stage Q row (128) and Qw row (256) in smem
    if (tid < DK) ((float*)sm_q4)[tid] = Q[(long)row * DK + tid];
    ((float*)sm_qw4)[tid] = g_qw[(long)row * DCTX + tid];
    __syncthreads();

    // Per-warp redundant qb = Q . b_ctx (cheap; avoids extra barrier)
    const float4 qv = sm_q4[lane];
    const float4 bv = ((const float4*)b_ctx)[lane];
    float qb = qv.x * bv.x + qv.y * bv.y + qv.z * bv.z + qv.w * bv.w;
#pragma unroll
    for (int off = 16; off; off >>= 1) qb += __shfl_xor_sync(~0u, qb, off);

    const float qmn = q_min[row];
    const float qmx = q_max[row];
    const float inv_sqrt = 0.08838834764831843f; // 1/sqrt(128)

    const long base_k = (long)row * KCAND * DK;   // K_kb / V_kb row base
    const long base_c = (long)row * KCAND * DCTX; // ctx_vec row base
    const float4 qwa = sm_qw4[lane];
    const float4 qwb = sm_qw4[lane + 32];

#pragma unroll
    for (int j = 0; j < 8; ++j) {
        const int k   = warp * 8 + j;
        const int rid = rel_id[row * KCAND + k];
        const int eid = ent_id[row * KCAND + k];

        // issue time-interval loads early (lane 0 consumes them after the
        // shuffle chain; LDG latency overlaps the reduction)
        const float tmin = tau_min[row * KCAND + k];
        const float tmax = tau_max[row * KCAND + k];

        const float4* kp = (const float4*)(K_kb   + base_k + (long)k * DK);
        const float4* rp = (const float4*)(rel_emb + (long)rid * DK);
        const float4* ep = (const float4*)(ent_emb + (long)eid * DK);
        const float4* cp = (const float4*)(ctx    + base_c + (long)k * DCTX);

        const float4 kv = kp[lane];            // coalesced 512B / warp
        const float4 rv = rp[lane];            // L2-hot gather, coalesced
        const float4 ev = ep[lane];
        const float4 c0 = cp[lane];            // coalesced
        const float4 c1 = cp[lane + 32];       // coalesced

        float sem = qv.x * kv.x + qv.y * kv.y + qv.z * kv.z + qv.w * kv.w;
        float cx  = qv.x * (rv.x + ev.x) + qv.y * (rv.y + ev.y)
                  + qv.z * (rv.z + ev.z) + qv.w * (rv.w + ev.w);
        cx += qwa.x * c0.x + qwa.y * c0.y + qwa.z * c0.z + qwa.w * c0.w;
        cx += qwb.x * c1.x + qwb.y * c1.y + qwb.z * c1.z + qwb.w * c1.w;

        float tot = sem + GAMMA * cx;
#pragma unroll
        for (int off = 16; off; off >>= 1) tot += __shfl_xor_sync(~0u, tot, off);

        if (lane == 0) {
            const float inter = fmaxf(fminf(qmx, tmax) - fmaxf(qmn, tmin), 0.f);
            const float uni   = fmaxf(qmx, tmax) - fminf(qmn, tmin);
            const float ts    = inter / (uni + 1e-6f);
            sm_s[k] = (tot + GAMMA * qb) * inv_sqrt + ETA * ts;
        }
    }
    __syncthreads();

    // Softmax over 64 scores (warp 0)
    if (warp == 0) {
        float s0 = sm_s[lane], s1 = sm_s[lane + 32];
        float m = fmaxf(s0, s1);
#pragma unroll
        for (int off = 16; off; off >>= 1) m = fmaxf(m, __shfl_xor_sync(~0u, m, off));
        float e0 = __expf((s0 - m) * INV_TEMP);
        float e1 = __expf((s1 - m) * INV_TEMP);
        float sum = e0 + e1;
#pragma unroll
        for (int off = 16; off; off >>= 1) sum += __shfl_xor_sync(~0u, sum, off);
        const float inv = 1.0f / sum;
        const float a0 = e0 * inv, a1 = e1 * inv;
        sm_s[lane]      = a0;
        sm_s[lane + 32] = a1;
        out_alpha[row * KCAND + lane]      = a0;
        out_alpha[row * KCAND + lane + 32] = a1;
    }
    __syncthreads();

    // V_tilde = sum_k alpha[k] * V_kb[k, :] — split k-range across 2 thread groups
    const int g = tid >> 7;        // 0 or 1
    const int d = tid & 127;
    const float* vb = V_kb + base_k + (long)g * 32 * DV;  // DV == DK so base_k works
    float acc = 0.f;
#pragma unroll 8
    for (int kk = 0; kk < 32; ++kk)
        acc = fmaf(sm_s[g * 32 + kk], vb[(long)kk * DV + d], acc);
    if (g) sm_vp[d] = acc;
    __syncthreads();
    if (!g) out_v[(long)row * DV + d] = acc + sm_vp[d];
}

// ---------------------------------------------------------------------------
extern "C" void kernel_launch(void* const* d_in, const int* in_sizes, int n_in,
                              void* d_out, int out_size) {
    const float* Q     = (const float*)d_in[0];
    const float* K_kb  = (const float*)d_in[1];
    const float* V_kb  = (const float*)d_in[2];
    const float* ctx   = (const float*)d_in[3];
    const float* W     = (const float*)d_in[4];
    const float* b_ctx = (const float*)d_in[5];
    const float* rel   = (const float*)d_in[6];
    const float* ent   = (const float*)d_in[7];
    const float* qmin  = (const float*)d_in[8];
    const float* qmax  = (const float*)d_in[9];
    const float* tmin  = (const float*)d_in[10];
    const float* tmax  = (const float*)d_in[11];
    const int*   rid   = (const int*)d_in[12];
    const int*   eid   = (const int*)d_in[13];

    float* out       = (float*)d_out;
    float* out_alpha = out;                    // [BT, 64]
    float* out_v     = out + BT * KCAND;       // [BT, 128]

    qw_kernel<<<BT / 16, 256>>>(Q, W);
    kb_main_kernel<<<BT, 256>>>(Q, K_kb, V_kb, ctx, b_ctx, rel, ent,
                                qmin, qmax, tmin, tmax, rid, eid,
                                out_alpha, out_v);
}

// round 3
// speedup vs baseline: 1.0511x; 1.0511x over previous
#include <cuda_runtime.h>

#define BT     4096      // B*T
#define KCAND  64
#define DK     128
#define DCTX   256
#define DV     128
#define GAMMA  1.0f
#define ETA    1.0f
#define INV_TEMP 1.0f

// 4 MB scratch for Qw = Q @ W_ctx  (device global => allowed, no allocation)
__device__ float g_qw[BT * DCTX];

#define CP_ASYNC_CG16(dst, src) \
    asm volatile("cp.async.cg.shared.global [%0], [%1], 16;\n" :: "r"(dst), "l"(src))
#define CP_ASYNC_COMMIT() asm volatile("cp.async.commit_group;\n" ::)
#define CP_ASYNC_WAIT0()  asm volatile("cp.async.wait_group 0;\n" ::)

__device__ __forceinline__ unsigned smem_u32(const void* p) {
    return (unsigned)__cvta_generic_to_shared(p);
}

// ---------------------------------------------------------------------------
// Kernel 1: Qw[row, c] = sum_d Q[row, d] * W_ctx[d, c]
// 8 rows per block => grid 512 (3.46 blocks/SM: good balance + latency hiding)
// ---------------------------------------------------------------------------
__global__ __launch_bounds__(256) void qw_kernel(const float* __restrict__ Q,
                                                 const float* __restrict__ W) {
    __shared__ float qsh[8][DK];
    const int rowbase = blockIdx.x * 8;
    for (int i = threadIdx.x; i < 8 * DK; i += 256)
        qsh[i >> 7][i & 127] = Q[rowbase * DK + i];
    __syncthreads();

    const int c = threadIdx.x;   // 0..255 = output column
    float acc[8];
#pragma unroll
    for (int r = 0; r < 8; ++r) acc[r] = 0.f;

#pragma unroll 4
    for (int d = 0; d < DK; ++d) {
        const float wv = W[d * DCTX + c];   // coalesced, L2-hot
#pragma unroll
        for (int r = 0; r < 8; ++r)
            acc[r] = fmaf(qsh[r][d], wv, acc[r]);  // smem broadcast
    }
#pragma unroll
    for (int r = 0; r < 8; ++r)
        g_qw[(rowbase + r) * DCTX + c] = acc[r];
}

// ---------------------------------------------------------------------------
// Kernel 2: one block per (b,t) row. 8 warps x 8 candidates.
// V tile (32KB) prefetched via cp.async, overlapping the score phase.
// ---------------------------------------------------------------------------
__global__ __launch_bounds__(256, 5) void kb_main_kernel(
    const float* __restrict__ Q,
    const float* __restrict__ K_kb,
    const float* __restrict__ V_kb,
    const float* __restrict__ ctx,
    const float* __restrict__ b_ctx,
    const float* __restrict__ rel_emb,
    const float* __restrict__ ent_emb,
    const float* __restrict__ q_min,
    const float* __restrict__ q_max,
    const float* __restrict__ tau_min,
    const float* __restrict__ tau_max,
    const int*   __restrict__ rel_id,
    const int*   __restrict__ ent_id,
    float* __restrict__ out_alpha,
    float* __restrict__ out_v)
{
    __shared__ float4 sm_v4[KCAND * DV / 4];   // 32 KB V tile
    __shared__ float4 sm_q4[DK / 4];           // 32 float4
    __shared__ float4 sm_qw4[DCTX / 4];        // 64 float4
    __shared__ float  sm_s[KCAND];             // scores -> alpha

    const int row  = blockIdx.x;
    const int tid  = threadIdx.x;
    const int warp = tid >> 5;
    const int lane = tid & 31;

    const long base_k = (long)row * KCAND * DK;   // K_kb / V_kb row base
    const long base_c = (long)row * KCAND * DCTX; // ctx_vec row base

    // Kick off async V-tile prefetch: 2048 float4, 8 per thread
    {
        const float4* vsrc = (const float4*)(V_kb + base_k);
        unsigned vdst = smem_u32(sm_v4);
#pragma unroll
        for (int i = 0; i < 8; ++i) {
            const int idx = tid + i * 256;
            CP_ASYNC_CG16(vdst + idx * 16, vsrc + idx);
        }
        CP_ASYNC_COMMIT();
    }

    // Stage Q row (128) and Qw row (256) in smem
    if (tid < DK) ((float*)sm_q4)[tid] = Q[(long)row * DK + tid];
    ((float*)sm_qw4)[tid] = g_qw[(long)row * DCTX + tid];
    __syncthreads();

    // Per-warp redundant qb = Q . b_ctx (cheap; avoids extra barrier)
    const float4 qv = sm_q4[lane];
    const float4 bv = ((const float4*)b_ctx)[lane];
    float qb = qv.x * bv.x + qv.y * bv.y + qv.z * bv.z + qv.w * bv.w;
#pragma unroll
    for (int off = 16; off; off >>= 1) qb += __shfl_xor_sync(~0u, qb, off);

    const float qmn = q_min[row];
    const float qmx = q_max[row];
    const float inv_sqrt = 0.08838834764831843f; // 1/sqrt(128)

    const float4 qwa = sm_qw4[lane];
    const float4 qwb = sm_qw4[lane + 32];

#pragma unroll
    for (int j = 0; j < 8; ++j) {
        const int k   = warp * 8 + j;
        const int rid = rel_id[row * KCAND + k];
        const int eid = ent_id[row * KCAND + k];

        // issued early; lane 0 consumes after the shuffle chain
        const float tmin = tau_min[row * KCAND + k];
        const float tmax = tau_max[row * KCAND + k];

        const float4* kp = (const float4*)(K_kb   + base_k + (long)k * DK);
        const float4* rp = (const float4*)(rel_emb + (long)rid * DK);
        const float4* ep = (const float4*)(ent_emb + (long)eid * DK);
        const float4* cp = (const float4*)(ctx    + base_c + (long)k * DCTX);

        const float4 kv = kp[lane];            // coalesced 512B / warp
        const float4 rv = rp[lane];            // L2-hot gather
        const float4 ev = ep[lane];
        const float4 c0 = cp[lane];            // coalesced
        const float4 c1 = cp[lane + 32];       // coalesced

        float sem = qv.x * kv.x + qv.y * kv.y + qv.z * kv.z + qv.w * kv.w;
        float cx  = qv.x * (rv.x + ev.x) + qv.y * (rv.y + ev.y)
                  + qv.z * (rv.z + ev.z) + qv.w * (rv.w + ev.w);
        cx += qwa.x * c0.x + qwa.y * c0.y + qwa.z * c0.z + qwa.w * c0.w;
        cx += qwb.x * c1.x + qwb.y * c1.y + qwb.z * c1.z + qwb.w * c1.w;

        float tot = sem + GAMMA * cx;
#pragma unroll
        for (int off = 16; off; off >>= 1) tot += __shfl_xor_sync(~0u, tot, off);

        if (lane == 0) {
            const float inter = fmaxf(fminf(qmx, tmax) - fmaxf(qmn, tmin), 0.f);
            const float uni   = fmaxf(qmx, tmax) - fminf(qmn, tmin);
            const float ts    = inter / (uni + 1e-6f);
            sm_s[k] = (tot + GAMMA * qb) * inv_sqrt + ETA * ts;
        }
    }
    CP_ASYNC_WAIT0();        // each thread's V copies done before barrier
    __syncthreads();         // scores visible + all V copies visible

    // Softmax over 64 scores (warp 0)
    if (warp == 0) {
        float s0 = sm_s[lane], s1 = sm_s[lane + 32];
        float m = fmaxf(s0, s1);
#pragma unroll
        for (int off = 16; off; off >>= 1) m = fmaxf(m, __shfl_xor_sync(~0u, m, off));
        float e0 = __expf((s0 - m) * INV_TEMP);
        float e1 = __expf((s1 - m) * INV_TEMP);
        float sum = e0 + e1;
#pragma unroll
        for (int off = 16; off; off >>= 1) sum += __shfl_xor_sync(~0u, sum, off);
        const float inv = 1.0f / sum;
        const float a0 = e0 * inv, a1 = e1 * inv;
        sm_s[lane]      = a0;
        sm_s[lane + 32] = a1;
        out_alpha[row * KCAND + lane]      = a0;
        out_alpha[row * KCAND + lane + 32] = a1;
    }
    __syncthreads();

    // V_tilde = sum_k alpha[k] * V[k, :] from smem — split k across 2 groups
    const int g = tid >> 7;        // 0 or 1
    const int d = tid & 127;
    const float* vs = (const float*)sm_v4 + g * 32 * DV;
    float acc = 0.f;
#pragma unroll
    for (int kk = 0; kk < 32; ++kk)
        acc = fmaf(sm_s[g * 32 + kk], vs[kk * DV + d], acc);
    // reuse sm_s region? too small — reuse sm_qw4 as the partial buffer
    float* sm_vp = (float*)sm_qw4;
    if (g) sm_vp[d] = acc;
    __syncthreads();
    if (!g) out_v[(long)row * DV + d] = acc + sm_vp[d];
}

// ---------------------------------------------------------------------------
extern "C" void kernel_launch(void* const* d_in, const int* in_sizes, int n_in,
                              void* d_out, int out_size) {
    const float* Q     = (const float*)d_in[0];
    const float* K_kb  = (const float*)d_in[1];
    const float* V_kb  = (const float*)d_in[2];
    const float* ctx   = (const float*)d_in[3];
    const float* W     = (const float*)d_in[4];
    const float* b_ctx = (const float*)d_in[5];
    const float* rel   = (const float*)d_in[6];
    const float* ent   = (const float*)d_in[7];
    const float* qmin  = (const float*)d_in[8];
    const float* qmax  = (const float*)d_in[9];
    const float* tmin  = (const float*)d_in[10];
    const float* tmax  = (const float*)d_in[11];
    const int*   rid   = (const int*)d_in[12];
    const int*   eid   = (const int*)d_in[13];

    float* out       = (float*)d_out;
    float* out_alpha = out;                    // [BT, 64]
    float* out_v     = out + BT * KCAND;       // [BT, 128]

    qw_kernel<<<BT / 8, 256>>>(Q, W);
    kb_main_kernel<<<BT, 256>>>(Q, K_kb, V_kb, ctx, b_ctx, rel, ent,
                                qmin, qmax, tmin, tmax, rid, eid,
                                out_alpha, out_v);
}